// round 9
// baseline (speedup 1.0000x reference)
#include <cuda_runtime.h>
#include <cuda_fp16.h>
#include <cstdint>

// Problem constants (C=32,H=32,W=32,KS=3, B=32)
constexpr int NDIM = 32 * 32 * 32 + 1;   // 32769
constexpr int KDIM = 32 * 3 * 3;         // 288
constexpr int BDIM = 32;

constexpr int WARPS_PER_BLOCK = 8;
constexpr int NBLK = (NDIM + WARPS_PER_BLOCK - 1) / WARPS_PER_BLOCK;  // 4097
constexpr int GRID = 148 * 4;   // 592: all-resident at 4 blocks/SM (<= 148*4, GB300 has 152 SMs)
constexpr int QCNT = KDIM / 32; // 9

// x transposed to [N, B] in fp16: each row is 64 B; one LDG.128 with 4-lane
// groups gathers EIGHT different rows per instruction.
__device__ __half g_xT[(size_t)NDIM * BDIM];

// Grid-barrier counter. Monotonic across graph replays: each launch consumes
// exactly GRID tickets, target is derived from the ticket itself, so no reset
// is needed and behavior is identical on every replay.
__device__ unsigned g_sync;

// ---------------------------------------------------------------------------
// Fused persistent kernel.
// Phase 1: transpose+fp16 convert x [B,N] -> x_T [N,B] (blocks split the rows)
// Grid barrier (all 592 blocks resident by construction)
// Phase 2: gather-dot, grid-stride over row-blocks.
// ---------------------------------------------------------------------------
__global__ __launch_bounds__(WARPS_PER_BLOCK * 32, 4)
void fused_kernel(const float* __restrict__ x,
                  const float* __restrict__ vals,
                  const int*   __restrict__ cols,
                  float*       __restrict__ out)
{
    __shared__ float s_acc[2][WARPS_PER_BLOCK][33];   // double-buffered

    // ---------------- Phase 1: transpose my share ----------------
    {
        const int gt = blockIdx.x * (WARPS_PER_BLOCK * 32) + threadIdx.x;
        for (int n = gt; n < NDIM; n += GRID * WARPS_PER_BLOCK * 32) {
            char* dst = (char*)g_xT + (size_t)n * 64;
            #pragma unroll
            for (int i = 0; i < 8; ++i) {
                // reads coalesced across the warp (consecutive n per lane)
                float f0 = __ldg(&x[(size_t)(4 * i + 0) * NDIM + n]);
                float f1 = __ldg(&x[(size_t)(4 * i + 1) * NDIM + n]);
                float f2 = __ldg(&x[(size_t)(4 * i + 2) * NDIM + n]);
                float f3 = __ldg(&x[(size_t)(4 * i + 3) * NDIM + n]);
                __half2 a = __floats2half2_rn(f0, f1);
                __half2 b = __floats2half2_rn(f2, f3);
                uint2 u;
                u.x = *(const unsigned*)&a;
                u.y = *(const unsigned*)&b;
                *(uint2*)(dst + i * 8) = u;   // 8B contiguous per i, 64B per n
            }
        }
    }

    // ---------------- Grid barrier (replay-safe, all blocks resident) -------
    __threadfence();      // publish x_T writes before arrival
    __syncthreads();      // whole block done writing before thread 0 arrives
    if (threadIdx.x == 0) {
        unsigned ticket = atomicAdd(&g_sync, 1u);
        unsigned target = (ticket / (unsigned)GRID) * (unsigned)GRID + (unsigned)GRID;
        while (atomicAdd(&g_sync, 0u) < target)
            __nanosleep(200);
        __threadfence();  // acquire: x_T writes from all blocks now visible
    }
    __syncthreads();

    // ---------------- Phase 2: gather-dot ----------------
    const int w    = threadIdx.x >> 5;
    const int lane = threadIdx.x & 31;
    const int g    = lane >> 2;   // group 0..7
    const int quad = lane & 3;    // 16B slice -> b = quad*8 .. quad*8+7

    int buf = 0;
    for (int rb = blockIdx.x; rb < NBLK; rb += GRID, buf ^= 1) {
        const int n = rb * WARPS_PER_BLOCK + w;

        float acc[8] = {0.f, 0.f, 0.f, 0.f, 0.f, 0.f, 0.f, 0.f};

        if (n < NDIM) {
            const int4*   cp = (const int4*)  (cols + (size_t)n * KDIM) + g;
            const float4* vp = (const float4*)(vals + (size_t)n * KDIM) + g;
            const char*   xb = (const char*)g_xT + quad * 16;

            int4   c = __ldg(cp);          // feed q=0 (1 wf across warp)
            float4 v = __ldg(vp);

            #pragma unroll
            for (int q = 0; q < QCNT; ++q) {
                uint4 h0 = __ldg((const uint4*)(xb + ((size_t)(unsigned)c.x << 6)));
                uint4 h1 = __ldg((const uint4*)(xb + ((size_t)(unsigned)c.y << 6)));
                uint4 h2 = __ldg((const uint4*)(xb + ((size_t)(unsigned)c.z << 6)));
                uint4 h3 = __ldg((const uint4*)(xb + ((size_t)(unsigned)c.w << 6)));
                float4 vc = v;

                if (q + 1 < QCNT) {
                    c = __ldg(cp + (q + 1) * 8);
                    v = __ldg(vp + (q + 1) * 8);
                }

                {
                    float2 f0 = __half22float2(*(const __half2*)&h0.x);
                    float2 f1 = __half22float2(*(const __half2*)&h0.y);
                    float2 f2 = __half22float2(*(const __half2*)&h0.z);
                    float2 f3 = __half22float2(*(const __half2*)&h0.w);
                    acc[0] = fmaf(vc.x, f0.x, acc[0]); acc[1] = fmaf(vc.x, f0.y, acc[1]);
                    acc[2] = fmaf(vc.x, f1.x, acc[2]); acc[3] = fmaf(vc.x, f1.y, acc[3]);
                    acc[4] = fmaf(vc.x, f2.x, acc[4]); acc[5] = fmaf(vc.x, f2.y, acc[5]);
                    acc[6] = fmaf(vc.x, f3.x, acc[6]); acc[7] = fmaf(vc.x, f3.y, acc[7]);
                }
                {
                    float2 f0 = __half22float2(*(const __half2*)&h1.x);
                    float2 f1 = __half22float2(*(const __half2*)&h1.y);
                    float2 f2 = __half22float2(*(const __half2*)&h1.z);
                    float2 f3 = __half22float2(*(const __half2*)&h1.w);
                    acc[0] = fmaf(vc.y, f0.x, acc[0]); acc[1] = fmaf(vc.y, f0.y, acc[1]);
                    acc[2] = fmaf(vc.y, f1.x, acc[2]); acc[3] = fmaf(vc.y, f1.y, acc[3]);
                    acc[4] = fmaf(vc.y, f2.x, acc[4]); acc[5] = fmaf(vc.y, f2.y, acc[5]);
                    acc[6] = fmaf(vc.y, f3.x, acc[6]); acc[7] = fmaf(vc.y, f3.y, acc[7]);
                }
                {
                    float2 f0 = __half22float2(*(const __half2*)&h2.x);
                    float2 f1 = __half22float2(*(const __half2*)&h2.y);
                    float2 f2 = __half22float2(*(const __half2*)&h2.z);
                    float2 f3 = __half22float2(*(const __half2*)&h2.w);
                    acc[0] = fmaf(vc.z, f0.x, acc[0]); acc[1] = fmaf(vc.z, f0.y, acc[1]);
                    acc[2] = fmaf(vc.z, f1.x, acc[2]); acc[3] = fmaf(vc.z, f1.y, acc[3]);
                    acc[4] = fmaf(vc.z, f2.x, acc[4]); acc[5] = fmaf(vc.z, f2.y, acc[5]);
                    acc[6] = fmaf(vc.z, f3.x, acc[6]); acc[7] = fmaf(vc.z, f3.y, acc[7]);
                }
                {
                    float2 f0 = __half22float2(*(const __half2*)&h3.x);
                    float2 f1 = __half22float2(*(const __half2*)&h3.y);
                    float2 f2 = __half22float2(*(const __half2*)&h3.z);
                    float2 f3 = __half22float2(*(const __half2*)&h3.w);
                    acc[0] = fmaf(vc.w, f0.x, acc[0]); acc[1] = fmaf(vc.w, f0.y, acc[1]);
                    acc[2] = fmaf(vc.w, f1.x, acc[2]); acc[3] = fmaf(vc.w, f1.y, acc[3]);
                    acc[4] = fmaf(vc.w, f2.x, acc[4]); acc[5] = fmaf(vc.w, f2.y, acc[5]);
                    acc[6] = fmaf(vc.w, f3.x, acc[6]); acc[7] = fmaf(vc.w, f3.y, acc[7]);
                }
            }
        }

        // Butterfly-reduce over the 8 groups (lane bits [2:4]).
        #pragma unroll
        for (int s = 4; s < 32; s <<= 1) {
            #pragma unroll
            for (int j = 0; j < 8; ++j)
                acc[j] += __shfl_xor_sync(0xffffffffu, acc[j], s);
        }

        if (lane < 4) {
            #pragma unroll
            for (int j = 0; j < 8; ++j)
                s_acc[buf][w][lane * 8 + j] = acc[j];
        }
        __syncthreads();   // single barrier; buffers alternate per iteration

        // Sector-coalesced store: thread t -> b = t/8, j = t%8.
        const int b  = threadIdx.x >> 3;
        const int j  = threadIdx.x & 7;
        const int nn = rb * WARPS_PER_BLOCK + j;
        if (nn < NDIM)
            out[(size_t)b * NDIM + nn] = s_acc[buf][j][b];
    }
}

// ---------------------------------------------------------------------------
// kernel_launch: inputs per metadata order: x_affine (f32), vals (f32), cols (i32)
// ---------------------------------------------------------------------------
extern "C" void kernel_launch(void* const* d_in, const int* in_sizes, int n_in,
                              void* d_out, int out_size)
{
    const float* x    = (const float*)d_in[0];
    const float* vals = (const float*)d_in[1];
    const int*   cols = (const int*)  d_in[2];
    float*       out  = (float*)d_out;

    (void)in_sizes; (void)n_in; (void)out_size;

    fused_kernel<<<GRID, WARPS_PER_BLOCK * 32>>>(x, vals, cols, out);
}